// round 6
// baseline (speedup 1.0000x reference)
#include <cuda_runtime.h>
#include <cstdint>

// ---------------- problem dims ----------------
// T=16, B=128, D=96, N=8, REL=96, OUT=64, EPS=1e-5
#define RELK 73728            // N*D*D per (t,b)
#define STEP_SMEM_FLOATS 27152
#define STEP_SMEM_BYTES (STEP_SMEM_FLOATS * 4)

// ---------------- device scratch (allocation-free rule) ----------------
__device__ float g_C2[(size_t)8 * 9216 * 64];                 // [n*9216+de][64] = 18.9MB
__device__ float g_cconst[64];
__device__ float g_relhist[(size_t)16 * 128 * RELK];          // 604MB

// ---------------- f32x2 packed helpers (sm_103a) ----------------
__device__ __forceinline__ unsigned long long pk2(float x, float y) {
    unsigned long long r;
    asm("mov.b64 %0, {%1, %2};" : "=l"(r) : "f"(x), "f"(y));
    return r;
}
__device__ __forceinline__ void fma2(unsigned long long& d, unsigned long long a, unsigned long long b) {
    asm("fma.rn.f32x2 %0, %1, %2, %0;" : "+l"(d) : "l"(a), "l"(b));
}
__device__ __forceinline__ void upk2(float& lo, float& hi, unsigned long long v) {
    asm("mov.b64 {%0, %1}, %2;" : "=f"(lo), "=f"(hi) : "l"(v));
}

// ---------------- precompute: C2[n,de,o] = sum_r Wr[de,r]*W3[n*96+r,o] ----
__global__ void __launch_bounds__(256, 1) c2_kernel(const float* __restrict__ Wr,
                                                    const float* __restrict__ W3) {
    __shared__ float Wrs[32 * 96];
    __shared__ float W3s[96 * 64];
    const int tid = threadIdx.x;
    const int de0 = blockIdx.x * 32;   // 288 de-tiles
    const int n = blockIdx.y;          // 8
    for (int p = tid; p < 3072; p += 256) Wrs[p] = Wr[de0 * 96 + p];
    for (int p = tid; p < 6144; p += 256) W3s[p] = W3[n * 6144 + p];
    __syncthreads();
    const int o = tid & 63, de_b = tid >> 6;
    float acc[8];
#pragma unroll
    for (int i = 0; i < 8; ++i) acc[i] = 0.f;
    for (int r = 0; r < 96; ++r) {
        float bv = W3s[r * 64 + o];
#pragma unroll
        for (int i = 0; i < 8; ++i)
            acc[i] = fmaf(Wrs[(de_b + 4 * i) * 96 + r], bv, acc[i]);
    }
#pragma unroll
    for (int i = 0; i < 8; ++i) {
        int de = de0 + de_b + 4 * i;
        g_C2[((size_t)n * 9216 + de) * 64 + o] = acc[i];
    }
}

// cconst[o] = b3[o] + sum_{nr} br[nr%96]*W3[nr,o]
__global__ void cconst_kernel(const float* __restrict__ br,
                              const float* __restrict__ W3,
                              const float* __restrict__ b3) {
    int o = threadIdx.x;  // 64
    float acc = b3[o];
    for (int nr = 0; nr < 768; ++nr)
        acc = fmaf(br[nr % 96], W3[nr * 64 + o], acc);
    g_cconst[o] = acc;
}

__global__ void init_out_kernel(float* __restrict__ out) {
    out[(size_t)blockIdx.x * 64 + threadIdx.x] = g_cconst[threadIdx.x];
}

// ---------------- phase 1: persistent recurrent kernel (1 block = 1 batch) ---
__global__ void __launch_bounds__(192, 1) step_kernel(
    const float* __restrict__ x,       // (16,128,96)
    const float* __restrict__ Wqkv,    // (96,24)
    const float* __restrict__ bqkv,    // (24)
    const float* __restrict__ ln_g,    // (96,24)
    const float* __restrict__ ln_b,    // (96,24)
    const float* __restrict__ pa1,
    const float* __restrict__ pa2,
    const float* __restrict__ pa3,
    const float* __restrict__ W2,      // (768,96)
    const float* __restrict__ b2,      // (96)
    const float* __restrict__ item_bias,  // (96,96)
    const float* __restrict__ rel_bias)   // (8,96,96)
{
    extern __shared__ float sm[];
    float* Mi   = sm;             // 96*100 = 9600   (pitch 100)
    float* tS2  = sm + 9600;      // 6144   layout [(n*96+d)*8 + j]
    float* qkvT = sm + 15744;     // 24*100 (row h, col d; pitch 100)
    float* WqT  = sm + 18144;     // 24*100 (WqT[h][f])
    float* lg   = sm + 20544;     // 2304   [d*24+h]
    float* lb   = sm + 22848;     // 2304
    float* Gp   = sm + 25152;     // 2*768 partials; final G at Gp[j*96+f]
    float* xts  = sm + 26688;     // 96
    float* vtr2 = sm + 26784;     // 192 partials; final Vtr in [0..95]
    float* xw   = sm + 26976;     // 32
    float* bq   = sm + 27008;     // 32
    float* b2s  = sm + 27040;     // 96
    float* red  = sm + 27136;     // 16

    const int tid = threadIdx.x;
    const int b = blockIdx.x;
    const float a1v = *pa1, a2v = *pa2, a3v = *pa3;

    // one-time loads
    for (int idx = tid; idx < 2304; idx += 192) {
        int f = idx / 24, h = idx % 24;
        WqT[h * 100 + f] = Wqkv[idx];
        lg[idx] = ln_g[idx];
        lb[idx] = ln_b[idx];
    }
    if (tid < 24) bq[tid] = bqkv[tid];
    if (tid < 96) b2s[tid] = b2[tid];
    for (int idx = tid; idx < 9216; idx += 192)
        Mi[(idx / 96) * 100 + (idx % 96)] = item_bias[idx];
    __syncthreads();

    for (int t = 0; t < 16; ++t) {
        if (tid < 96) xts[tid] = x[(t * 128 + b) * 96 + tid];
        __syncthreads();

        // op1: Mi += x x^T
        for (int idx = tid; idx < 9216; idx += 192) {
            int d = idx / 96, f = idx % 96;
            Mi[d * 100 + f] = fmaf(xts[d], xts[f], Mi[d * 100 + f]);
        }
        __syncthreads();

        const float* relp = (t == 0) ? rel_bias
                            : (g_relhist + ((size_t)(t - 1) * 128 + b) * RELK);

        // op2: Vtr[f] = sum_{n,d} Mi[d,f]*rel[n,d,f]  (d split over 2 groups)
        {
            int f = tid % 96, g = tid / 96;
            int d0 = g * 48;
            float acc = 0.f;
            for (int n = 0; n < 8; ++n) {
                const float* rp = relp + (n * 96 + d0) * 96 + f;
                const float* mp = Mi + d0 * 100 + f;
#pragma unroll 4
                for (int d = 0; d < 48; ++d)
                    acc = fmaf(mp[d * 100], rp[d * 96], acc);
            }
            vtr2[tid] = acc;
        }
        __syncthreads();
        if (tid < 96) vtr2[tid] += vtr2[tid + 96];
        if (tid >= 96 && tid < 120) {      // xw[h] = sum_f x[f]*Wqkv[f,h]
            int h = tid - 96;
            float acc = 0.f;
            for (int f = 0; f < 96; ++f)
                acc = fmaf(xts[f], WqT[h * 100 + f], acc);
            xw[h] = acc;
        }
        __syncthreads();

        // op3: qkv[d,h] = sum_f Mi[d,f]*Wqkv[f,h] + a2*Vtr[d]*xw[h] + bqkv[h]
        // stored transposed into qkvT[h][d]; accumulate LN stats.
        float s1 = 0.f, s2 = 0.f;
        {
            int dt = tid / 8, ht = tid % 8;
            int d0 = dt * 4, h0 = ht * 3;
            float acc[4][3];
#pragma unroll
            for (int i = 0; i < 4; ++i)
#pragma unroll
                for (int j = 0; j < 3; ++j)
                    acc[i][j] = bq[h0 + j] + a2v * vtr2[d0 + i] * xw[h0 + j];
#pragma unroll 4
            for (int f4 = 0; f4 < 24; ++f4) {
                float4 m4[4], w4[3];
#pragma unroll
                for (int i = 0; i < 4; ++i)
                    m4[i] = *(const float4*)&Mi[(d0 + i) * 100 + f4 * 4];
#pragma unroll
                for (int j = 0; j < 3; ++j)
                    w4[j] = *(const float4*)&WqT[(h0 + j) * 100 + f4 * 4];
#pragma unroll
                for (int i = 0; i < 4; ++i)
#pragma unroll
                    for (int j = 0; j < 3; ++j) {
                        acc[i][j] = fmaf(m4[i].x, w4[j].x, acc[i][j]);
                        acc[i][j] = fmaf(m4[i].y, w4[j].y, acc[i][j]);
                        acc[i][j] = fmaf(m4[i].z, w4[j].z, acc[i][j]);
                        acc[i][j] = fmaf(m4[i].w, w4[j].w, acc[i][j]);
                    }
            }
#pragma unroll
            for (int i = 0; i < 4; ++i)
#pragma unroll
                for (int j = 0; j < 3; ++j) {
                    float v = acc[i][j];
                    qkvT[(h0 + j) * 100 + (d0 + i)] = v;
                    s1 += v;
                    s2 = fmaf(v, v, s2);
                }
        }
        // LN reduction over 2304 elements
#pragma unroll
        for (int o = 16; o > 0; o >>= 1) {
            s1 += __shfl_down_sync(0xffffffffu, s1, o);
            s2 += __shfl_down_sync(0xffffffffu, s2, o);
        }
        if ((tid & 31) == 0) { red[(tid >> 5) * 2] = s1; red[(tid >> 5) * 2 + 1] = s2; }
        __syncthreads();
        if (tid == 0) {
            float S = 0.f, SS = 0.f;
            for (int w = 0; w < 6; ++w) { S += red[w * 2]; SS += red[w * 2 + 1]; }
            float mu = S * (1.f / 2304.f);
            float var = SS * (1.f / 2304.f) - mu * mu;
            red[12] = mu;
            red[13] = rsqrtf(var + 1e-5f);
        }
        __syncthreads();
        const float mu = red[12], rstd = red[13];

        // op4: LN apply in place
        for (int idx = tid; idx < 2304; idx += 192) {
            int h = idx / 96, d = idx % 96;
            float v = qkvT[h * 100 + d];
            qkvT[h * 100 + d] = (v - mu) * rstd * lg[d * 24 + h] + lb[d * 24 + h];
        }
        __syncthreads();

        // op5: t[n][d][j] = tanh(q[n][d]*k[j][d]) via exp (robust, accurate)
        for (int idx = tid; idx < 6144; idx += 192) {
            int j = idx & 7, d = (idx >> 3) % 96, n = idx / 768;
            float p = qkvT[n * 100 + d] * qkvT[(8 + j) * 100 + d];
            float e = __expf(2.f * p);
            tS2[(n * 96 + d) * 8 + j] = 1.f - 2.f / (e + 1.f);
        }
        __syncthreads();

        // op6: G[j][f] = sum_{n,d} t[n][j][d]*W2[(n*96+d)*96+f]  (f32x2, d split 2)
        {
            int f = tid % 96, g = tid / 96;
            int d0 = g * 48;
            unsigned long long accP[4];
#pragma unroll
            for (int jj = 0; jj < 4; ++jj) accP[jj] = 0ull;
            for (int n = 0; n < 8; ++n) {
                const float* w2p = W2 + (n * 96 + d0) * 96 + f;
                const float4* tp = (const float4*)&tS2[(n * 96 + d0) * 8];
#pragma unroll 4
                for (int d = 0; d < 48; ++d) {
                    float w = w2p[d * 96];
                    unsigned long long wp = pk2(w, w);
                    float4 t0 = tp[d * 2], t1 = tp[d * 2 + 1];
                    fma2(accP[0], wp, pk2(t0.x, t0.y));
                    fma2(accP[1], wp, pk2(t0.z, t0.w));
                    fma2(accP[2], wp, pk2(t1.x, t1.y));
                    fma2(accP[3], wp, pk2(t1.z, t1.w));
                }
            }
#pragma unroll
            for (int jj = 0; jj < 4; ++jj) {
                float lo, hi;
                upk2(lo, hi, accP[jj]);
                Gp[g * 768 + (2 * jj) * 96 + f] = lo;
                Gp[g * 768 + (2 * jj + 1) * 96 + f] = hi;
            }
        }
        __syncthreads();
        for (int idx = tid; idx < 768; idx += 192) Gp[idx] += Gp[768 + idx];
        __syncthreads();

        // op7: Mi[e][f] += a3*( sum_j v[j][e]*G[j][f] + b2[f] )
        {
            int e = tid >> 1, half = tid & 1;
            float ve[8];
#pragma unroll
            for (int j = 0; j < 8; ++j) ve[j] = qkvT[(16 + j) * 100 + e];
#pragma unroll 3
            for (int q = 0; q < 12; ++q) {
                int f0 = half * 48 + q * 4;
                float ax = 0.f, ay = 0.f, az = 0.f, aw = 0.f;
#pragma unroll
                for (int j = 0; j < 8; ++j) {
                    float4 g4 = *(const float4*)&Gp[j * 96 + f0];
                    ax = fmaf(ve[j], g4.x, ax);
                    ay = fmaf(ve[j], g4.y, ay);
                    az = fmaf(ve[j], g4.z, az);
                    aw = fmaf(ve[j], g4.w, aw);
                }
                float4 b4 = *(const float4*)&b2s[f0];
                float4 m4 = *(float4*)&Mi[e * 100 + f0];
                m4.x = fmaf(a3v, ax + b4.x, m4.x);
                m4.y = fmaf(a3v, ay + b4.y, m4.y);
                m4.z = fmaf(a3v, az + b4.z, m4.z);
                m4.w = fmaf(a3v, aw + b4.w, m4.w);
                *(float4*)&Mi[e * 100 + f0] = m4;
            }
        }

        // op8: rel_new[n,d,e] = a1*rel_old + sum_j t[n][j][d]*v[j][e]  (f32x2 pairs)
        {
            int ep = tid % 48, g = tid / 48;
            int e0 = 2 * ep;
            unsigned long long vP[8];
#pragma unroll
            for (int j = 0; j < 8; ++j)
                vP[j] = *(const unsigned long long*)&qkvT[(16 + j) * 100 + e0];
            float* relo = g_relhist + ((size_t)t * 128 + b) * RELK;
            const unsigned long long a1P = pk2(a1v, a1v);
            for (int it = g; it < 768; it += 4) {
                const float4* tp = (const float4*)&tS2[it * 8];
                float4 t0 = tp[0], t1 = tp[1];
                unsigned long long rP = *(const unsigned long long*)&relp[it * 96 + e0];
                unsigned long long acc = 0ull;
                fma2(acc, a1P, rP);
                fma2(acc, pk2(t0.x, t0.x), vP[0]);
                fma2(acc, pk2(t0.y, t0.y), vP[1]);
                fma2(acc, pk2(t0.z, t0.z), vP[2]);
                fma2(acc, pk2(t0.w, t0.w), vP[3]);
                fma2(acc, pk2(t1.x, t1.x), vP[4]);
                fma2(acc, pk2(t1.y, t1.y), vP[5]);
                fma2(acc, pk2(t1.z, t1.z), vP[6]);
                fma2(acc, pk2(t1.w, t1.w), vP[7]);
                *(unsigned long long*)&relo[it * 96 + e0] = acc;
            }
        }
        __syncthreads();
    }
}

// ---------------- phase 2: out += relhist @ C2   (M=2048, K=73728, N=64) -----
// grid (8 M-tiles of 256, 36 K-splits of 2048), 256 thr, 2 CTAs/SM.
__global__ void __launch_bounds__(256, 2) out_gemm_kernel(float* __restrict__ out) {
    __shared__ float As[256][36];   // pitch 36: 16B-aligned rows, conflict-free
    __shared__ float Bs[32][64];
    const int tid = threadIdx.x;
    const int m0 = blockIdx.x * 256;
    const int k0 = blockIdx.y * 2048;
    const int cg = tid & 7, rg = tid >> 3;
    unsigned long long acc[8][4];
#pragma unroll
    for (int i = 0; i < 8; ++i)
#pragma unroll
        for (int j = 0; j < 4; ++j) acc[i][j] = 0ull;

    for (int kc = 0; kc < 2048; kc += 32) {
#pragma unroll
        for (int it = 0; it < 8; ++it) {
            int idx = it * 256 + tid;
            int r = idx >> 3, q = idx & 7;
            *(float4*)&As[r][q * 4] =
                *(const float4*)&g_relhist[(size_t)(m0 + r) * RELK + k0 + kc + q * 4];
        }
#pragma unroll
        for (int it = 0; it < 2; ++it) {
            int idx = it * 256 + tid;
            int kr = idx >> 4, q = idx & 15;
            *(float4*)&Bs[kr][q * 4] =
                *(const float4*)&g_C2[(size_t)(k0 + kc + kr) * 64 + q * 4];
        }
        __syncthreads();
#pragma unroll
        for (int k = 0; k < 32; ++k) {
            unsigned long long bP[4];
#pragma unroll
            for (int j = 0; j < 4; ++j)
                bP[j] = *(const unsigned long long*)&Bs[k][cg * 8 + 2 * j];
#pragma unroll
            for (int i = 0; i < 8; ++i) {
                float a = As[rg + 32 * i][k];
                unsigned long long aP = pk2(a, a);
#pragma unroll
                for (int j = 0; j < 4; ++j) fma2(acc[i][j], aP, bP[j]);
            }
        }
        __syncthreads();
    }
#pragma unroll
    for (int i = 0; i < 8; ++i) {
        int m = m0 + rg + 32 * i;
#pragma unroll
        for (int j = 0; j < 4; ++j) {
            float lo, hi;
            upk2(lo, hi, acc[i][j]);
            atomicAdd(&out[(size_t)m * 64 + cg * 8 + 2 * j], lo);
            atomicAdd(&out[(size_t)m * 64 + cg * 8 + 2 * j + 1], hi);
        }
    }
}

// ---------------- launch ----------------
extern "C" void kernel_launch(void* const* d_in, const int* in_sizes, int n_in,
                              void* d_out, int out_size) {
    const float* x         = (const float*)d_in[0];
    const float* Wqkv      = (const float*)d_in[1];
    const float* bqkv      = (const float*)d_in[2];
    const float* ln_g      = (const float*)d_in[3];
    const float* ln_b      = (const float*)d_in[4];
    const float* a1        = (const float*)d_in[5];
    const float* a2        = (const float*)d_in[6];
    const float* a3        = (const float*)d_in[7];
    const float* W2        = (const float*)d_in[8];
    const float* b2        = (const float*)d_in[9];
    const float* Wr        = (const float*)d_in[10];
    const float* br        = (const float*)d_in[11];
    const float* W3        = (const float*)d_in[12];
    const float* b3        = (const float*)d_in[13];
    const float* item_bias = (const float*)d_in[14];
    const float* rel_bias  = (const float*)d_in[15];
    float* out = (float*)d_out;

    cudaFuncSetAttribute(step_kernel, cudaFuncAttributeMaxDynamicSharedMemorySize,
                         STEP_SMEM_BYTES);

    c2_kernel<<<dim3(288, 8), 256>>>(Wr, W3);
    cconst_kernel<<<1, 64>>>(br, W3, b3);
    init_out_kernel<<<2048, 64>>>(out);
    step_kernel<<<128, 192, STEP_SMEM_BYTES>>>(x, Wqkv, bqkv, ln_g, ln_b,
                                               a1, a2, a3, W2, b2,
                                               item_bias, rel_bias);
    out_gemm_kernel<<<dim3(8, 36), 256>>>(out);
}

// round 8
// speedup vs baseline: 1.4945x; 1.4945x over previous
#include <cuda_runtime.h>
#include <cstdint>

typedef unsigned long long ull;

// ---------------- problem dims ----------------
// T=16, B=128, D=96, N=8, REL=96, OUT=64, EPS=1e-5
#define RELK 73728            // N*D*D per (t,b)

// ---------------- smem layout for step_kernel (float offsets) ----------------
#define SM_MI     0            // 96*100
#define SM_RELSUM 9600         // 9216
#define SM_TDUP   18816        // 12288 floats = 6144 ull, [(n*96+d)*8+j] = (t,t)
#define SM_QKVT   31104        // 24*100
#define SM_WQT    33504        // 24*100
#define SM_LG     35904        // 2304
#define SM_LB     38208        // 2304
#define SM_GPART  40512        // 8*768
#define SM_XTS    46656        // 96
#define SM_VTR4   46752        // 384
#define SM_VTRF   47136        // 96
#define SM_XW     47232        // 32
#define SM_BQ     47264        // 32
#define SM_B2S    47296        // 96
#define SM_RED    47392        // 32
#define STEP_SMEM_FLOATS 47424
#define STEP_SMEM_BYTES (STEP_SMEM_FLOATS * 4)   // 189,696 B

// ---------------- device scratch (allocation-free rule) ----------------
__device__ float g_C2[(size_t)8 * 9216 * 64];                 // 18.9MB
__device__ float g_cconst[64];
__device__ float g_relsum0[9216];
__device__ float g_relhist[(size_t)16 * 128 * RELK];          // 604MB

// ---------------- f32x2 packed helpers (sm_103a) ----------------
__device__ __forceinline__ ull pk2(float x, float y) {
    ull r;
    asm("mov.b64 %0, {%1, %2};" : "=l"(r) : "f"(x), "f"(y));
    return r;
}
__device__ __forceinline__ void fma2(ull& d, ull a, ull b) {
    asm("fma.rn.f32x2 %0, %1, %2, %0;" : "+l"(d) : "l"(a), "l"(b));
}
__device__ __forceinline__ void add2(ull& d, ull a) {
    asm("add.rn.f32x2 %0, %0, %1;" : "+l"(d) : "l"(a));
}
__device__ __forceinline__ void upk2(float& lo, float& hi, ull v) {
    asm("mov.b64 {%0, %1}, %2;" : "=f"(lo), "=f"(hi) : "l"(v));
}

// ---------------- precompute: C2[n,de,o] = sum_r Wr[de,r]*W3[n*96+r,o] ----
__global__ void __launch_bounds__(256, 1) c2_kernel(const float* __restrict__ Wr,
                                                    const float* __restrict__ W3) {
    __shared__ float Wrs[32 * 96];
    __shared__ float W3s[96 * 64];
    const int tid = threadIdx.x;
    const int de0 = blockIdx.x * 32;   // 288 de-tiles
    const int n = blockIdx.y;          // 8
    for (int p = tid; p < 3072; p += 256) Wrs[p] = Wr[de0 * 96 + p];
    for (int p = tid; p < 6144; p += 256) W3s[p] = W3[n * 6144 + p];
    __syncthreads();
    const int o = tid & 63, de_b = tid >> 6;
    float acc[8];
#pragma unroll
    for (int i = 0; i < 8; ++i) acc[i] = 0.f;
    for (int r = 0; r < 96; ++r) {
        float bv = W3s[r * 64 + o];
#pragma unroll
        for (int i = 0; i < 8; ++i)
            acc[i] = fmaf(Wrs[(de_b + 4 * i) * 96 + r], bv, acc[i]);
    }
#pragma unroll
    for (int i = 0; i < 8; ++i) {
        int de = de0 + de_b + 4 * i;
        g_C2[((size_t)n * 9216 + de) * 64 + o] = acc[i];
    }
}

// cconst[o] = b3[o] + sum_{nr} br[nr%96]*W3[nr,o]
__global__ void cconst_kernel(const float* __restrict__ br,
                              const float* __restrict__ W3,
                              const float* __restrict__ b3) {
    int o = threadIdx.x;  // 64
    float acc = b3[o];
    for (int nr = 0; nr < 768; ++nr)
        acc = fmaf(br[nr % 96], W3[nr * 64 + o], acc);
    g_cconst[o] = acc;
}

// relsum0[d*96+e] = sum_n rel_bias[n,d,e]
__global__ void relsum0_kernel(const float* __restrict__ rb) {
    int idx = blockIdx.x * 256 + threadIdx.x;
    if (idx < 9216) {
        float s = 0.f;
#pragma unroll
        for (int n = 0; n < 8; ++n) s += rb[n * 9216 + idx];
        g_relsum0[idx] = s;
    }
}

__global__ void init_out_kernel(float* __restrict__ out) {
    out[(size_t)blockIdx.x * 64 + threadIdx.x] = g_cconst[threadIdx.x];
}

// ---------------- phase 1: persistent recurrent kernel (1 block = 1 batch) ---
__global__ void __launch_bounds__(384, 1) step_kernel(
    const float* __restrict__ x,       // (16,128,96)
    const float* __restrict__ Wqkv,    // (96,24)
    const float* __restrict__ bqkv,    // (24)
    const float* __restrict__ ln_g,    // (96,24)
    const float* __restrict__ ln_b,    // (96,24)
    const float* __restrict__ pa1,
    const float* __restrict__ pa2,
    const float* __restrict__ pa3,
    const float* __restrict__ W2,      // (768,96)
    const float* __restrict__ b2,      // (96)
    const float* __restrict__ item_bias,  // (96,96)
    const float* __restrict__ rel_bias)   // (8,96,96)
{
    extern __shared__ float sm[];
    float* Mi     = sm + SM_MI;
    float* relsum = sm + SM_RELSUM;
    ull*   tdup   = (ull*)(sm + SM_TDUP);
    float* qkvT   = sm + SM_QKVT;
    float* WqT    = sm + SM_WQT;
    float* lg     = sm + SM_LG;
    float* lb     = sm + SM_LB;
    float* Gpart  = sm + SM_GPART;
    float* xts    = sm + SM_XTS;
    float* vtr4   = sm + SM_VTR4;
    float* vtrF   = sm + SM_VTRF;
    float* xw     = sm + SM_XW;
    float* bq     = sm + SM_BQ;
    float* b2s    = sm + SM_B2S;
    float* red    = sm + SM_RED;

    const int tid = threadIdx.x;
    const int b = blockIdx.x;
    const float a1v = *pa1, a2v = *pa2, a3v = *pa3;

    // one-time loads
    for (int idx = tid; idx < 2304; idx += 384) {
        int f = idx / 24, h = idx % 24;
        WqT[h * 100 + f] = Wqkv[idx];
        lg[idx] = ln_g[idx];
        lb[idx] = ln_b[idx];
    }
    if (tid < 24) bq[tid] = bqkv[tid];
    if (tid < 96) b2s[tid] = b2[tid];
    for (int idx = tid; idx < 9216; idx += 384) {
        Mi[(idx / 96) * 100 + (idx % 96)] = item_bias[idx];
        relsum[idx] = g_relsum0[idx];
    }
    __syncthreads();

    for (int t = 0; t < 16; ++t) {
        if (tid < 96) xts[tid] = x[(t * 128 + b) * 96 + tid];
        __syncthreads();

        // op1: Mi += x x^T
        for (int idx = tid; idx < 9216; idx += 384) {
            int d = idx / 96, f = idx % 96;
            Mi[d * 100 + f] = fmaf(xts[d], xts[f], Mi[d * 100 + f]);
        }
        __syncthreads();

        // Vtr partials (via relsum — no rel re-read!) and xw
        {
            int f = tid % 96, q = tid / 96;
            int d0 = q * 24;
            float acc = 0.f;
#pragma unroll 6
            for (int d = d0; d < d0 + 24; ++d)
                acc = fmaf(Mi[d * 100 + f], relsum[d * 96 + f], acc);
            vtr4[q * 96 + f] = acc;
        }
        if (tid < 24) {
            float acc = 0.f;
            for (int f = 0; f < 96; ++f)
                acc = fmaf(xts[f], WqT[tid * 100 + f], acc);
            xw[tid] = acc;
        }
        __syncthreads();
        if (tid < 96)
            vtrF[tid] = vtr4[tid] + vtr4[96 + tid] + vtr4[192 + tid] + vtr4[288 + tid];
        __syncthreads();

        // op3: qkv[d,h] = Mi[d,:]·Wqkv[:,h] + a2*Vtr[d]*xw[h] + bqkv[h]   (f32x2)
        float s1 = 0.f, s2 = 0.f;
        {
            const int dt = tid / 12, ht = tid % 12;
            const int d0 = dt * 3, h0 = ht * 2;
            ull acc2[3][2];
#pragma unroll
            for (int i = 0; i < 3; ++i)
#pragma unroll
                for (int j = 0; j < 2; ++j) acc2[i][j] = 0ull;
#pragma unroll 8
            for (int fp = 0; fp < 48; ++fp) {
                ull m0 = *(const ull*)&Mi[(d0 + 0) * 100 + 2 * fp];
                ull m1 = *(const ull*)&Mi[(d0 + 1) * 100 + 2 * fp];
                ull m2 = *(const ull*)&Mi[(d0 + 2) * 100 + 2 * fp];
                ull w0 = *(const ull*)&WqT[(h0 + 0) * 100 + 2 * fp];
                ull w1 = *(const ull*)&WqT[(h0 + 1) * 100 + 2 * fp];
                fma2(acc2[0][0], m0, w0); fma2(acc2[0][1], m0, w1);
                fma2(acc2[1][0], m1, w0); fma2(acc2[1][1], m1, w1);
                fma2(acc2[2][0], m2, w0); fma2(acc2[2][1], m2, w1);
            }
#pragma unroll
            for (int i = 0; i < 3; ++i)
#pragma unroll
                for (int j = 0; j < 2; ++j) {
                    float lo, hi;
                    upk2(lo, hi, acc2[i][j]);
                    float v = lo + hi + bq[h0 + j] + a2v * vtrF[d0 + i] * xw[h0 + j];
                    qkvT[(h0 + j) * 100 + (d0 + i)] = v;
                    s1 += v;
                    s2 = fmaf(v, v, s2);
                }
        }
        // LN reduction over 2304 elements
#pragma unroll
        for (int o = 16; o > 0; o >>= 1) {
            s1 += __shfl_down_sync(0xffffffffu, s1, o);
            s2 += __shfl_down_sync(0xffffffffu, s2, o);
        }
        if ((tid & 31) == 0) { red[(tid >> 5) * 2] = s1; red[(tid >> 5) * 2 + 1] = s2; }
        __syncthreads();
        if (tid == 0) {
            float S = 0.f, SS = 0.f;
            for (int w = 0; w < 12; ++w) { S += red[w * 2]; SS += red[w * 2 + 1]; }
            float mu = S * (1.f / 2304.f);
            float var = SS * (1.f / 2304.f) - mu * mu;
            red[30] = mu;
            red[31] = rsqrtf(var + 1e-5f);
        }
        __syncthreads();
        const float mu = red[30], rstd = red[31];

        // op4: LN apply in place
        for (int idx = tid; idx < 2304; idx += 384) {
            int h = idx / 96, d = idx % 96;
            float v = qkvT[h * 100 + d];
            qkvT[h * 100 + d] = (v - mu) * rstd * lg[d * 24 + h] + lb[d * 24 + h];
        }
        __syncthreads();

        // op5: tdup[(n*96+d)*8+j] = (tanh(q[n,d]*k[j,d]), same)
        for (int idx = tid; idx < 6144; idx += 384) {
            int j = idx & 7, d = (idx >> 3) % 96, n = idx / 768;
            float p = qkvT[n * 100 + d] * qkvT[(8 + j) * 100 + d];
            float e = __expf(2.f * p);
            float tv = 1.f - 2.f / (e + 1.f);
            tdup[idx] = pk2(tv, tv);
        }
        __syncthreads();

        // op6: Gpart[g][j][f-pair] = sum_{nd in group g} t[nd][j] * W2[nd][f-pair]
        {
            const int fp = tid % 48, g = tid / 48;
            const int f0 = 2 * fp;
            ull acc[8];
#pragma unroll
            for (int j = 0; j < 8; ++j) acc[j] = 0ull;
            const float* w2p = W2 + (g * 96) * 96 + f0;
            const ulonglong2* tp = (const ulonglong2*)&tdup[(g * 96) * 8];
#pragma unroll 4
            for (int m = 0; m < 96; ++m) {
                ull w = *(const ull*)&w2p[m * 96];
                ulonglong2 t01 = tp[m * 4 + 0];
                ulonglong2 t23 = tp[m * 4 + 1];
                ulonglong2 t45 = tp[m * 4 + 2];
                ulonglong2 t67 = tp[m * 4 + 3];
                fma2(acc[0], t01.x, w); fma2(acc[1], t01.y, w);
                fma2(acc[2], t23.x, w); fma2(acc[3], t23.y, w);
                fma2(acc[4], t45.x, w); fma2(acc[5], t45.y, w);
                fma2(acc[6], t67.x, w); fma2(acc[7], t67.y, w);
            }
#pragma unroll
            for (int j = 0; j < 8; ++j)
                *(ull*)&Gpart[g * 768 + j * 96 + f0] = acc[j];
        }
        __syncthreads();
        // reduce Gpart over the 8 groups -> G in Gpart[0..767]
        for (int idx = tid; idx < 768; idx += 384) {
            float s = Gpart[idx];
#pragma unroll
            for (int g2 = 1; g2 < 8; ++g2) s += Gpart[g2 * 768 + idx];
            Gpart[idx] = s;
        }
        __syncthreads();

        // op7: Mi[e][f] += a3*( sum_j v[j][e]*G[j][f] + b2[f] )
        {
            const int e = tid >> 2, part = tid & 3;
            const int f0b = part * 24;
            ull vp[8];
#pragma unroll
            for (int j = 0; j < 8; ++j) {
                float ve = qkvT[(16 + j) * 100 + e];
                vp[j] = pk2(ve, ve);
            }
#pragma unroll 3
            for (int q = 0; q < 12; ++q) {
                int f0 = f0b + q * 2;
                ull acc = 0ull;
#pragma unroll
                for (int j = 0; j < 8; ++j)
                    fma2(acc, vp[j], *(const ull*)&Gpart[j * 96 + f0]);
                float lo, hi;
                upk2(lo, hi, acc);
                Mi[e * 100 + f0]     = fmaf(a3v, lo + b2s[f0],     Mi[e * 100 + f0]);
                Mi[e * 100 + f0 + 1] = fmaf(a3v, hi + b2s[f0 + 1], Mi[e * 100 + f0 + 1]);
            }
        }

        // op8: rel_new = a1*rel_old + sum_j t[nd][j]*v[j][e-pair]; relsum folded in
        {
            const int ep = tid % 48, g = tid / 48;
            const int e0 = 2 * ep;
            ull vP[8];
#pragma unroll
            for (int j = 0; j < 8; ++j)
                vP[j] = *(const ull*)&qkvT[(16 + j) * 100 + e0];
            const float* relp = (t == 0) ? rel_bias
                                : (g_relhist + ((size_t)(t - 1) * 128 + b) * RELK);
            float* relo = g_relhist + ((size_t)t * 128 + b) * RELK;
            const ull a1P = pk2(a1v, a1v);
            ull racc[12];
#pragma unroll
            for (int dd = 0; dd < 12; ++dd) racc[dd] = 0ull;
            for (int n = 0; n < 8; ++n) {
#pragma unroll
                for (int dd = 0; dd < 12; ++dd) {
                    int it = n * 96 + g + 8 * dd;
                    ull acc = 0ull;
                    fma2(acc, a1P, *(const ull*)&relp[it * 96 + e0]);
                    const ulonglong2* tp = (const ulonglong2*)&tdup[it * 8];
                    ulonglong2 t01 = tp[0], t23 = tp[1], t45 = tp[2], t67 = tp[3];
                    fma2(acc, t01.x, vP[0]); fma2(acc, t01.y, vP[1]);
                    fma2(acc, t23.x, vP[2]); fma2(acc, t23.y, vP[3]);
                    fma2(acc, t45.x, vP[4]); fma2(acc, t45.y, vP[5]);
                    fma2(acc, t67.x, vP[6]); fma2(acc, t67.y, vP[7]);
                    *(ull*)&relo[it * 96 + e0] = acc;
                    add2(racc[dd], acc);
                }
            }
#pragma unroll
            for (int dd = 0; dd < 12; ++dd)
                *(ull*)&relsum[(g + 8 * dd) * 96 + e0] = racc[dd];
        }
        __syncthreads();
    }
}

// ---------------- phase 2: out += relhist @ C2   (M=2048, K=73728, N=64) -----
// A stored pre-duplicated as (a,a) ull pairs, pitch 33 ull -> conflict-free.
#define G2_AS_ULL (256 * 33)
#define G2_SMEM_BYTES (G2_AS_ULL * 8 + 32 * 64 * 4)   // 67584 + 8192 = 75776
__global__ void __launch_bounds__(256, 2) out_gemm_kernel(float* __restrict__ out) {
    extern __shared__ ull smu[];
    ull* As2 = smu;                          // [256][33] (dup pairs)
    float* Bs = (float*)(smu + G2_AS_ULL);   // [32][64]
    const int tid = threadIdx.x;
    const int m0 = blockIdx.x * 256;
    const int k0 = blockIdx.y * 2048;
    const int cg = tid & 7, rg = tid >> 3;
    ull acc[8][4];
#pragma unroll
    for (int i = 0; i < 8; ++i)
#pragma unroll
        for (int j = 0; j < 4; ++j) acc[i][j] = 0ull;

    for (int kc = 0; kc < 2048; kc += 32) {
#pragma unroll
        for (int it = 0; it < 8; ++it) {
            int idx = it * 256 + tid;
            int r = idx >> 3, q = idx & 7;
            float4 v = *(const float4*)&g_relhist[(size_t)(m0 + r) * RELK + k0 + kc + q * 4];
            ull* dst = &As2[r * 33 + q * 4];
            dst[0] = pk2(v.x, v.x);
            dst[1] = pk2(v.y, v.y);
            dst[2] = pk2(v.z, v.z);
            dst[3] = pk2(v.w, v.w);
        }
#pragma unroll
        for (int it = 0; it < 2; ++it) {
            int idx = it * 256 + tid;
            int kr = idx >> 4, q = idx & 15;
            *(float4*)&Bs[kr * 64 + q * 4] =
                *(const float4*)&g_C2[(size_t)(k0 + kc + kr) * 64 + q * 4];
        }
        __syncthreads();
#pragma unroll
        for (int k = 0; k < 32; ++k) {
            ull bP[4];
#pragma unroll
            for (int j = 0; j < 4; ++j)
                bP[j] = *(const ull*)&Bs[k * 64 + cg * 8 + 2 * j];
#pragma unroll
            for (int i = 0; i < 8; ++i) {
                ull aP = As2[(rg + 32 * i) * 33 + k];
#pragma unroll
                for (int j = 0; j < 4; ++j) fma2(acc[i][j], aP, bP[j]);
            }
        }
        __syncthreads();
    }
#pragma unroll
    for (int i = 0; i < 8; ++i) {
        int m = m0 + rg + 32 * i;
#pragma unroll
        for (int j = 0; j < 4; ++j) {
            float lo, hi;
            upk2(lo, hi, acc[i][j]);
            atomicAdd(&out[(size_t)m * 64 + cg * 8 + 2 * j], lo);
            atomicAdd(&out[(size_t)m * 64 + cg * 8 + 2 * j + 1], hi);
        }
    }
}

// ---------------- launch ----------------
extern "C" void kernel_launch(void* const* d_in, const int* in_sizes, int n_in,
                              void* d_out, int out_size) {
    const float* x         = (const float*)d_in[0];
    const float* Wqkv      = (const float*)d_in[1];
    const float* bqkv      = (const float*)d_in[2];
    const float* ln_g      = (const float*)d_in[3];
    const float* ln_b      = (const float*)d_in[4];
    const float* a1        = (const float*)d_in[5];
    const float* a2        = (const float*)d_in[6];
    const float* a3        = (const float*)d_in[7];
    const float* W2        = (const float*)d_in[8];
    const float* b2        = (const float*)d_in[9];
    const float* Wr        = (const float*)d_in[10];
    const float* br        = (const float*)d_in[11];
    const float* W3        = (const float*)d_in[12];
    const float* b3        = (const float*)d_in[13];
    const float* item_bias = (const float*)d_in[14];
    const float* rel_bias  = (const float*)d_in[15];
    float* out = (float*)d_out;

    cudaFuncSetAttribute(step_kernel, cudaFuncAttributeMaxDynamicSharedMemorySize,
                         STEP_SMEM_BYTES);
    cudaFuncSetAttribute(out_gemm_kernel, cudaFuncAttributeMaxDynamicSharedMemorySize,
                         G2_SMEM_BYTES);

    c2_kernel<<<dim3(288, 8), 256>>>(Wr, W3);
    cconst_kernel<<<1, 64>>>(br, W3, b3);
    relsum0_kernel<<<36, 256>>>(rel_bias);
    init_out_kernel<<<2048, 64>>>(out);
    step_kernel<<<128, 384, STEP_SMEM_BYTES>>>(x, Wqkv, bqkv, ln_g, ln_b,
                                               a1, a2, a3, W2, b2,
                                               item_bias, rel_bias);
    out_gemm_kernel<<<dim3(8, 36), 256, G2_SMEM_BYTES>>>(out);
}